// round 1
// baseline (speedup 1.0000x reference)
#include <cuda_runtime.h>
#include <math.h>

#define BB 16
#define SS 1024
#define DD 768
#define HH 12
#define DHH 64
#define NROWS (BB*SS)   // 16384

// Scratch: Q/K/V in [B,H,S,DH] layout (head-major, DH contiguous)
__device__ float g_Q[BB*HH*SS*DHH];
__device__ float g_K[BB*HH*SS*DHH];
__device__ float g_V[BB*HH*SS*DHH];

// ---------------------------------------------------------------------------
// Kernel 1: fused QKV projection.  C[n,m] = sum_k X[n,k] * W[m,k] + b[m]
// (NT GEMM, both operands K-contiguous). blockIdx.z selects Q/K/V.
// 128x128 tile, BK=16, 256 threads, 8x8 microtile.
// Writes directly into [B,H,S,DH] layout.
// ---------------------------------------------------------------------------
__global__ __launch_bounds__(256) void qkv_kernel(
    const float* __restrict__ X,
    const float* __restrict__ Wq, const float* __restrict__ bq,
    const float* __restrict__ Wk, const float* __restrict__ bk,
    const float* __restrict__ Wv, const float* __restrict__ bv)
{
    const int which = blockIdx.z;
    const float* W    = (which == 0) ? Wq : (which == 1) ? Wk : Wv;
    const float* bias = (which == 0) ? bq : (which == 1) ? bk : bv;
    float* out        = (which == 0) ? g_Q : (which == 1) ? g_K : g_V;

    __shared__ float As[16][132];  // X tile, transposed: As[k][row]
    __shared__ float Bs[16][132];  // W tile, transposed: Bs[k][col]

    const int tid = threadIdx.x;
    const int tx = tid & 15;       // 0..15 -> 8 output cols each
    const int ty = tid >> 4;       // 0..15 -> 8 output rows each
    const int n0 = blockIdx.y * 128;
    const int m0 = blockIdx.x * 128;

    float acc[8][8];
    #pragma unroll
    for (int i = 0; i < 8; i++)
        #pragma unroll
        for (int j = 0; j < 8; j++) acc[i][j] = 0.0f;

    for (int k0 = 0; k0 < DD; k0 += 16) {
        // cooperative load: 128 rows x 16 k of X and W, transposed into smem
        #pragma unroll
        for (int l = 0; l < 2; l++) {
            int f   = tid + l * 256;       // 0..511  (512 float4 per matrix)
            int row = f >> 2;              // 0..127
            int kc  = (f & 3) * 4;         // 0,4,8,12
            float4 v = *(const float4*)(X + (size_t)(n0 + row) * DD + k0 + kc);
            As[kc + 0][row] = v.x; As[kc + 1][row] = v.y;
            As[kc + 2][row] = v.z; As[kc + 3][row] = v.w;
            float4 w = *(const float4*)(W + (size_t)(m0 + row) * DD + k0 + kc);
            Bs[kc + 0][row] = w.x; Bs[kc + 1][row] = w.y;
            Bs[kc + 2][row] = w.z; Bs[kc + 3][row] = w.w;
        }
        __syncthreads();

        #pragma unroll
        for (int k = 0; k < 16; k++) {
            float a[8], b[8];
            *(float4*)&a[0] = *(const float4*)&As[k][ty * 8];
            *(float4*)&a[4] = *(const float4*)&As[k][ty * 8 + 4];
            *(float4*)&b[0] = *(const float4*)&Bs[k][tx * 8];
            *(float4*)&b[4] = *(const float4*)&Bs[k][tx * 8 + 4];
            #pragma unroll
            for (int i = 0; i < 8; i++)
                #pragma unroll
                for (int j = 0; j < 8; j++)
                    acc[i][j] += a[i] * b[j];
        }
        __syncthreads();
    }

    // epilogue: add bias, scatter into [B,H,S,DH]
    #pragma unroll
    for (int i = 0; i < 8; i++) {
        int n = n0 + ty * 8 + i;
        int b_idx = n >> 10;        // n / 1024
        int s_idx = n & 1023;
        #pragma unroll
        for (int j = 0; j < 8; j++) {
            int m = m0 + tx * 8 + j;
            int h = m >> 6;
            int d = m & 63;
            out[(((size_t)b_idx * HH + h) * SS + s_idx) * DHH + d] =
                acc[i][j] + bias[m];
        }
    }
}

// ---------------------------------------------------------------------------
// Kernel 2: flash attention (fp32, online softmax).
// One block = one (b,h) and one 64-row q-tile. 256 threads (16x16),
// 4x4 microtile. K/V streamed in 64-row tiles. Ks buffer reused for P.
// Static smem: 3 * 64*64*4 = 48 KB.
// ---------------------------------------------------------------------------
__global__ __launch_bounds__(256) void attn_kernel(float* __restrict__ out)
{
    __shared__ float Qs[64][64];   // [d][qrow]   (transposed)
    __shared__ float Ks[64][64];   // [d][krow]; reused as Ps[qrow][kk]
    __shared__ float Vs[64][64];   // [kk][d]

    const int tid = threadIdx.x;
    const int tx = tid & 15;       // 4 cols each
    const int ty = tid >> 4;       // 4 rows each
    const int bh = blockIdx.y;     // b*H + h
    const int q0 = blockIdx.x * 64;
    const int b  = bh / HH;
    const int h  = bh % HH;

    const float* Qg = g_Q + (size_t)bh * SS * DHH + (size_t)q0 * DHH;
    const float* Kg = g_K + (size_t)bh * SS * DHH;
    const float* Vg = g_V + (size_t)bh * SS * DHH;

    // load Q tile transposed: Qs[d][row]
    for (int f = tid; f < 64 * 16; f += 256) {
        int row = f >> 4;
        int dc  = (f & 15) * 4;
        float4 v = *(const float4*)(Qg + (size_t)row * DHH + dc);
        Qs[dc + 0][row] = v.x; Qs[dc + 1][row] = v.y;
        Qs[dc + 2][row] = v.z; Qs[dc + 3][row] = v.w;
    }

    float m_i[4], l_i[4], o[4][4];
    #pragma unroll
    for (int i = 0; i < 4; i++) {
        m_i[i] = -1e30f;
        l_i[i] = 0.0f;
        #pragma unroll
        for (int j = 0; j < 4; j++) o[i][j] = 0.0f;
    }

    const float scale = 0.125f;    // 1/sqrt(64)

    for (int kt = 0; kt < 16; kt++) {
        __syncthreads();  // prev-tile P/V reads done; also covers Q-load for kt=0

        const float* Kt = Kg + (size_t)kt * 64 * DHH;
        const float* Vt = Vg + (size_t)kt * 64 * DHH;
        for (int f = tid; f < 64 * 16; f += 256) {
            int row = f >> 4;
            int dc  = (f & 15) * 4;
            float4 v = *(const float4*)(Kt + (size_t)row * DHH + dc);
            Ks[dc + 0][row] = v.x; Ks[dc + 1][row] = v.y;
            Ks[dc + 2][row] = v.z; Ks[dc + 3][row] = v.w;
            float4 w = *(const float4*)(Vt + (size_t)row * DHH + dc);
            *(float4*)&Vs[row][dc] = w;
        }
        __syncthreads();

        // S = (Q K^T) * scale   (64x64 tile, reduce over d)
        float s[4][4];
        #pragma unroll
        for (int i = 0; i < 4; i++)
            #pragma unroll
            for (int j = 0; j < 4; j++) s[i][j] = 0.0f;

        for (int d = 0; d < 64; d++) {
            float4 qv = *(const float4*)&Qs[d][ty * 4];
            float4 kv = *(const float4*)&Ks[d][tx * 4];
            float qa[4] = {qv.x, qv.y, qv.z, qv.w};
            float ka[4] = {kv.x, kv.y, kv.z, kv.w};
            #pragma unroll
            for (int i = 0; i < 4; i++)
                #pragma unroll
                for (int j = 0; j < 4; j++)
                    s[i][j] += qa[i] * ka[j];
        }

        // online softmax (row stats reduced across the 16 tx lanes)
        #pragma unroll
        for (int i = 0; i < 4; i++) {
            #pragma unroll
            for (int j = 0; j < 4; j++) s[i][j] *= scale;

            float mx = fmaxf(fmaxf(s[i][0], s[i][1]), fmaxf(s[i][2], s[i][3]));
            #pragma unroll
            for (int off = 1; off < 16; off <<= 1)
                mx = fmaxf(mx, __shfl_xor_sync(0xffffffffu, mx, off));

            float mnew  = fmaxf(m_i[i], mx);
            float alpha = __expf(m_i[i] - mnew);
            m_i[i] = mnew;

            float rsum = 0.0f;
            #pragma unroll
            for (int j = 0; j < 4; j++) {
                s[i][j] = __expf(s[i][j] - mnew);
                rsum += s[i][j];
            }
            #pragma unroll
            for (int off = 1; off < 16; off <<= 1)
                rsum += __shfl_xor_sync(0xffffffffu, rsum, off);

            l_i[i] = l_i[i] * alpha + rsum;
            #pragma unroll
            for (int j = 0; j < 4; j++) o[i][j] *= alpha;
        }

        __syncthreads();  // everyone done reading Ks -> safe to overwrite with P

        // store P into Ks buffer as Ps[qrow][kk] (stride 64)
        float* Ps = &Ks[0][0];
        #pragma unroll
        for (int i = 0; i < 4; i++) {
            float4 p4 = make_float4(s[i][0], s[i][1], s[i][2], s[i][3]);
            *(float4*)&Ps[(ty * 4 + i) * 64 + tx * 4] = p4;
        }
        __syncthreads();

        // O += P * V   (reduce over kk)
        for (int kk = 0; kk < 64; kk++) {
            float4 vv = *(const float4*)&Vs[kk][tx * 4];
            float va[4] = {vv.x, vv.y, vv.z, vv.w};
            #pragma unroll
            for (int i = 0; i < 4; i++) {
                float p = Ps[(ty * 4 + i) * 64 + kk];
                #pragma unroll
                for (int j = 0; j < 4; j++) o[i][j] += p * va[j];
            }
        }
    }

    // write output: out[b, s, h*64 + d]  (normalize by l)
    #pragma unroll
    for (int i = 0; i < 4; i++) {
        float inv = 1.0f / l_i[i];
        int srow = q0 + ty * 4 + i;
        float4 r = make_float4(o[i][0] * inv, o[i][1] * inv,
                               o[i][2] * inv, o[i][3] * inv);
        *(float4*)(out + ((size_t)b * SS + srow) * DD + h * DHH + tx * 4) = r;
    }
}

// ---------------------------------------------------------------------------
extern "C" void kernel_launch(void* const* d_in, const int* in_sizes, int n_in,
                              void* d_out, int out_size)
{
    const float* X  = (const float*)d_in[0];
    const float* Wq = (const float*)d_in[1];
    const float* bq = (const float*)d_in[2];
    const float* Wk = (const float*)d_in[3];
    const float* bk = (const float*)d_in[4];
    const float* Wv = (const float*)d_in[5];
    const float* bv = (const float*)d_in[6];
    float* out = (float*)d_out;

    dim3 g1(DD / 128, NROWS / 128, 3);   // (6, 128, 3)
    qkv_kernel<<<g1, 256>>>(X, Wq, bq, Wk, bk, Wv, bv);

    dim3 g2(SS / 64, BB * HH);           // (16, 192)
    attn_kernel<<<g2, 256>>>(out);
}

// round 4
// speedup vs baseline: 3.2497x; 3.2497x over previous
#include <cuda_runtime.h>
#include <cstdint>
#include <math.h>

#define BB 16
#define SS 1024
#define DD 768
#define HH 12
#define DHH 64
#define NROWS (BB*SS)   // 16384

// Scratch: Q/K/V in [B,H,S,DH] layout (head-major, DH contiguous)
__device__ float g_Q[BB*HH*SS*DHH];
__device__ float g_K[BB*HH*SS*DHH];
__device__ float g_V[BB*HH*SS*DHH];

// ---------------------------------------------------------------------------
// helpers
// ---------------------------------------------------------------------------
__device__ __forceinline__ uint32_t f2tf32(float x) {
    uint32_t t;
    asm("cvt.rna.tf32.f32 %0, %1;" : "=r"(t) : "f"(x));
    return t;
}

// D = A*B + D,  m16n8k8, tf32 inputs, fp32 accum
__device__ __forceinline__ void mma_tf32(float c[4],
                                         uint32_t a0, uint32_t a1, uint32_t a2, uint32_t a3,
                                         uint32_t b0, uint32_t b1) {
    asm volatile(
        "mma.sync.aligned.m16n8k8.row.col.f32.tf32.tf32.f32 "
        "{%0,%1,%2,%3}, {%4,%5,%6,%7}, {%8,%9}, {%0,%1,%2,%3};"
        : "+f"(c[0]), "+f"(c[1]), "+f"(c[2]), "+f"(c[3])
        : "r"(a0), "r"(a1), "r"(a2), "r"(a3), "r"(b0), "r"(b1));
}

// ===========================================================================
// Kernel 1: QKV projection, C[n,m] = sum_k X[n,k] W[m,k] + b[m]
// 128x128 tile, BK=32, 256 threads (8 warps: 2m x 4n), warp tile 64x32.
// smem padded stride 36 (banks: 4*row + col -> conflict-free frag loads).
// ===========================================================================
#define QKV_STRIDE 36
__global__ __launch_bounds__(256) void qkv_mma_kernel(
    const float* __restrict__ X,
    const float* __restrict__ Wq, const float* __restrict__ bq,
    const float* __restrict__ Wk, const float* __restrict__ bk,
    const float* __restrict__ Wv, const float* __restrict__ bv)
{
    __shared__ uint32_t As[128 * QKV_STRIDE];
    __shared__ uint32_t Bs[128 * QKV_STRIDE];

    const int which = blockIdx.z;
    const float* W    = (which == 0) ? Wq : (which == 1) ? Wk : Wv;
    const float* bias = (which == 0) ? bq : (which == 1) ? bk : bv;
    float* out        = (which == 0) ? g_Q : (which == 1) ? g_K : g_V;

    const int tid = threadIdx.x;
    const int wid = tid >> 5;
    const int lane = tid & 31;
    const int g   = lane >> 2;     // groupID
    const int tig = lane & 3;      // threadID in group
    const int wm = wid >> 2;       // 0..1
    const int wn = wid & 3;        // 0..3
    const int n0 = blockIdx.y * 128;
    const int m0 = blockIdx.x * 128;

    const float* srcA = X + (size_t)n0 * DD;
    const float* srcB = W + (size_t)m0 * DD;

    float acc[4][4][4];
    #pragma unroll
    for (int mt = 0; mt < 4; mt++)
        #pragma unroll
        for (int nt = 0; nt < 4; nt++)
            #pragma unroll
            for (int r = 0; r < 4; r++) acc[mt][nt][r] = 0.0f;

    float4 ra[4], rb[4];
    // prefetch stage 0
    #pragma unroll
    for (int l = 0; l < 4; l++) {
        int idx = tid + l * 256;
        int row = idx >> 3, c4 = (idx & 7) * 4;
        ra[l] = *(const float4*)(srcA + (size_t)row * DD + c4);
        rb[l] = *(const float4*)(srcB + (size_t)row * DD + c4);
    }

    for (int s = 0; s < DD / 32; s++) {
        // store current stage to smem (cvt to tf32)
        #pragma unroll
        for (int l = 0; l < 4; l++) {
            int idx = tid + l * 256;
            int row = idx >> 3, c4 = (idx & 7) * 4;
            uint4 at = make_uint4(f2tf32(ra[l].x), f2tf32(ra[l].y),
                                  f2tf32(ra[l].z), f2tf32(ra[l].w));
            uint4 bt = make_uint4(f2tf32(rb[l].x), f2tf32(rb[l].y),
                                  f2tf32(rb[l].z), f2tf32(rb[l].w));
            *(uint4*)&As[row * QKV_STRIDE + c4] = at;
            *(uint4*)&Bs[row * QKV_STRIDE + c4] = bt;
        }
        __syncthreads();

        // prefetch next stage
        if (s + 1 < DD / 32) {
            const int k0 = (s + 1) * 32;
            #pragma unroll
            for (int l = 0; l < 4; l++) {
                int idx = tid + l * 256;
                int row = idx >> 3, c4 = (idx & 7) * 4;
                ra[l] = *(const float4*)(srcA + (size_t)row * DD + k0 + c4);
                rb[l] = *(const float4*)(srcB + (size_t)row * DD + k0 + c4);
            }
        }

        // 4 k-steps of 8
        #pragma unroll
        for (int ks = 0; ks < 4; ks++) {
            const int kc = ks * 8 + tig;
            uint32_t bf[4][2];
            #pragma unroll
            for (int nt = 0; nt < 4; nt++) {
                int col = wn * 32 + nt * 8 + g;
                bf[nt][0] = Bs[col * QKV_STRIDE + kc];
                bf[nt][1] = Bs[col * QKV_STRIDE + kc + 4];
            }
            #pragma unroll
            for (int mt = 0; mt < 4; mt++) {
                int row = wm * 64 + mt * 16 + g;
                uint32_t a0 = As[row * QKV_STRIDE + kc];
                uint32_t a1 = As[(row + 8) * QKV_STRIDE + kc];
                uint32_t a2 = As[row * QKV_STRIDE + kc + 4];
                uint32_t a3 = As[(row + 8) * QKV_STRIDE + kc + 4];
                #pragma unroll
                for (int nt = 0; nt < 4; nt++)
                    mma_tf32(acc[mt][nt], a0, a1, a2, a3, bf[nt][0], bf[nt][1]);
            }
        }
        __syncthreads();
    }

    // epilogue: bias + scatter to [B,H,S,DH]
    #pragma unroll
    for (int mt = 0; mt < 4; mt++) {
        #pragma unroll
        for (int half = 0; half < 2; half++) {
            int n = n0 + wm * 64 + mt * 16 + g + half * 8;
            int b_idx = n >> 10;
            int s_idx = n & 1023;
            #pragma unroll
            for (int nt = 0; nt < 4; nt++) {
                int col = m0 + wn * 32 + nt * 8 + 2 * tig;
                int h = col >> 6, d = col & 63;
                float2 v;
                v.x = acc[mt][nt][half * 2 + 0] + bias[col];
                v.y = acc[mt][nt][half * 2 + 1] + bias[col + 1];
                *(float2*)(out + (((size_t)b_idx * HH + h) * SS + s_idx) * DHH + d) = v;
            }
        }
    }
}

// ===========================================================================
// Kernel 2: flash attention with tf32 mma.sync.
// Block: one (b,h), q-tile 128 rows. 256 threads = 8 warps x 16 q-rows.
// K/V streamed in 64-token tiles. All smem padded to stride 68 floats
// (272B rows, 16B aligned).
// ===========================================================================
#define AT_STRIDE 68
#define Q_OFF 0
#define K_OFF (128 * AT_STRIDE)
#define V_OFF (K_OFF + 64 * AT_STRIDE)
#define P_OFF (V_OFF + 64 * AT_STRIDE)
#define AT_SMEM_FLOATS (P_OFF + 128 * AT_STRIDE)
#define AT_SMEM_BYTES (AT_SMEM_FLOATS * 4)   // 104448

__global__ __launch_bounds__(256) void attn_mma_kernel(float* __restrict__ out)
{
    extern __shared__ uint32_t sm[];
    uint32_t* Qs = sm + Q_OFF;
    uint32_t* Ks = sm + K_OFF;
    uint32_t* Vs = sm + V_OFF;
    uint32_t* Ps = sm + P_OFF;

    const int tid = threadIdx.x;
    const int wid = tid >> 5;
    const int lane = tid & 31;
    const int g   = lane >> 2;
    const int tig = lane & 3;
    const int bh = blockIdx.y;
    const int q0 = blockIdx.x * 128;
    const int b  = bh / HH;
    const int h  = bh % HH;

    const float* Qg = g_Q + (size_t)bh * SS * DHH + (size_t)q0 * DHH;
    const float* Kg = g_K + (size_t)bh * SS * DHH;
    const float* Vg = g_V + (size_t)bh * SS * DHH;

    // load Q tile (128 x 64) -> tf32 smem  (128*16 = 2048 float4 = 256*8)
    #pragma unroll
    for (int l = 0; l < 8; l++) {
        int idx = tid + l * 256;
        int row = idx >> 4, c4 = (idx & 15) * 4;
        float4 v = *(const float4*)(Qg + (size_t)row * DHH + c4);
        uint4 t = make_uint4(f2tf32(v.x), f2tf32(v.y), f2tf32(v.z), f2tf32(v.w));
        *(uint4*)&Qs[row * AT_STRIDE + c4] = t;
    }

    float o[8][4];
    float m_i[2], l_i[2];
    #pragma unroll
    for (int nt = 0; nt < 8; nt++)
        #pragma unroll
        for (int r = 0; r < 4; r++) o[nt][r] = 0.0f;
    m_i[0] = m_i[1] = -1e30f;
    l_i[0] = l_i[1] = 0.0f;

    const int arow = wid * 16 + g;          // this thread's base q-row (a-frag)
    const float scale = 0.125f;

    for (int kt = 0; kt < 16; kt++) {
        __syncthreads();   // prev PV done reading Vs; also covers Q load at kt=0

        // load K,V tiles (64 x 64 each): 64*16 = 1024 float4 each = 256*4
        const float* Kt = Kg + (size_t)kt * 64 * DHH;
        const float* Vt = Vg + (size_t)kt * 64 * DHH;
        #pragma unroll
        for (int l = 0; l < 4; l++) {
            int idx = tid + l * 256;
            int row = idx >> 4, c4 = (idx & 15) * 4;
            float4 v = *(const float4*)(Kt + (size_t)row * DHH + c4);
            float4 w = *(const float4*)(Vt + (size_t)row * DHH + c4);
            uint4 tk = make_uint4(f2tf32(v.x), f2tf32(v.y), f2tf32(v.z), f2tf32(v.w));
            uint4 tv = make_uint4(f2tf32(w.x), f2tf32(w.y), f2tf32(w.z), f2tf32(w.w));
            *(uint4*)&Ks[row * AT_STRIDE + c4] = tk;
            *(uint4*)&Vs[row * AT_STRIDE + c4] = tv;
        }
        __syncthreads();

        // --- S = Q @ K^T (warp: 16 x 64) ---
        float sfr[8][4];
        #pragma unroll
        for (int nt = 0; nt < 8; nt++)
            #pragma unroll
            for (int r = 0; r < 4; r++) sfr[nt][r] = 0.0f;

        #pragma unroll
        for (int ks = 0; ks < 8; ks++) {
            const int kc = ks * 8 + tig;
            uint32_t a0 = Qs[arow * AT_STRIDE + kc];
            uint32_t a1 = Qs[(arow + 8) * AT_STRIDE + kc];
            uint32_t a2 = Qs[arow * AT_STRIDE + kc + 4];
            uint32_t a3 = Qs[(arow + 8) * AT_STRIDE + kc + 4];
            #pragma unroll
            for (int nt = 0; nt < 8; nt++) {
                int tok = nt * 8 + g;
                uint32_t b0 = Ks[tok * AT_STRIDE + kc];
                uint32_t b1 = Ks[tok * AT_STRIDE + kc + 4];
                mma_tf32(sfr[nt], a0, a1, a2, a3, b0, b1);
            }
        }

        // --- online softmax (rows arow and arow+8) ---
        #pragma unroll
        for (int half = 0; half < 2; half++) {
            float mx = -1e30f;
            #pragma unroll
            for (int nt = 0; nt < 8; nt++) {
                sfr[nt][half * 2 + 0] *= scale;
                sfr[nt][half * 2 + 1] *= scale;
                mx = fmaxf(mx, fmaxf(sfr[nt][half * 2], sfr[nt][half * 2 + 1]));
            }
            mx = fmaxf(mx, __shfl_xor_sync(0xffffffffu, mx, 1));
            mx = fmaxf(mx, __shfl_xor_sync(0xffffffffu, mx, 2));

            float mnew  = fmaxf(m_i[half], mx);
            float alpha = __expf(m_i[half] - mnew);
            m_i[half] = mnew;

            float rsum = 0.0f;
            #pragma unroll
            for (int nt = 0; nt < 8; nt++) {
                float p0 = __expf(sfr[nt][half * 2 + 0] - mnew);
                float p1 = __expf(sfr[nt][half * 2 + 1] - mnew);
                sfr[nt][half * 2 + 0] = p0;
                sfr[nt][half * 2 + 1] = p1;
                rsum += p0 + p1;
            }
            rsum += __shfl_xor_sync(0xffffffffu, rsum, 1);
            rsum += __shfl_xor_sync(0xffffffffu, rsum, 2);

            l_i[half] = l_i[half] * alpha + rsum;
            #pragma unroll
            for (int nt = 0; nt < 8; nt++) {
                o[nt][half * 2 + 0] *= alpha;
                o[nt][half * 2 + 1] *= alpha;
            }
        }

        // --- store P (tf32) to smem; warp-local rows only ---
        #pragma unroll
        for (int nt = 0; nt < 8; nt++) {
            int cc = nt * 8 + 2 * tig;
            uint2 p0 = make_uint2(f2tf32(sfr[nt][0]), f2tf32(sfr[nt][1]));
            uint2 p1 = make_uint2(f2tf32(sfr[nt][2]), f2tf32(sfr[nt][3]));
            *(uint2*)&Ps[arow * AT_STRIDE + cc] = p0;
            *(uint2*)&Ps[(arow + 8) * AT_STRIDE + cc] = p1;
        }
        __syncwarp();   // each warp reads only its own P rows

        // --- O += P @ V (k-dim = 64 tokens) ---
        #pragma unroll
        for (int ks = 0; ks < 8; ks++) {
            const int kc = ks * 8 + tig;
            uint32_t a0 = Ps[arow * AT_STRIDE + kc];
            uint32_t a1 = Ps[(arow + 8) * AT_STRIDE + kc];
            uint32_t a2 = Ps[arow * AT_STRIDE + kc + 4];
            uint32_t a3 = Ps[(arow + 8) * AT_STRIDE + kc + 4];
            #pragma unroll
            for (int nt = 0; nt < 8; nt++) {
                int dcol = nt * 8 + g;
                uint32_t b0 = Vs[kc * AT_STRIDE + dcol];
                uint32_t b1 = Vs[(kc + 4) * AT_STRIDE + dcol];
                mma_tf32(o[nt], a0, a1, a2, a3, b0, b1);
            }
        }
    }

    // --- finalize: normalize + write out[b, s, h*64+d] ---
    #pragma unroll
    for (int half = 0; half < 2; half++) {
        float inv = 1.0f / l_i[half];
        int srow = q0 + arow + half * 8;
        float* dst = out + ((size_t)b * SS + srow) * DD + h * DHH;
        #pragma unroll
        for (int nt = 0; nt < 8; nt++) {
            int d = nt * 8 + 2 * tig;
            float2 v = make_float2(o[nt][half * 2] * inv, o[nt][half * 2 + 1] * inv);
            *(float2*)(dst + d) = v;
        }
    }
}

// ---------------------------------------------------------------------------
extern "C" void kernel_launch(void* const* d_in, const int* in_sizes, int n_in,
                              void* d_out, int out_size)
{
    const float* X  = (const float*)d_in[0];
    const float* Wq = (const float*)d_in[1];
    const float* bq = (const float*)d_in[2];
    const float* Wk = (const float*)d_in[3];
    const float* bk = (const float*)d_in[4];
    const float* Wv = (const float*)d_in[5];
    const float* bv = (const float*)d_in[6];
    float* out = (float*)d_out;

    cudaFuncSetAttribute(attn_mma_kernel,
                         cudaFuncAttributeMaxDynamicSharedMemorySize, AT_SMEM_BYTES);

    dim3 g1(DD / 128, NROWS / 128, 3);   // (6, 128, 3)
    qkv_mma_kernel<<<g1, 256>>>(X, Wq, bq, Wk, bk, Wv, bv);

    dim3 g2(SS / 128, BB * HH);          // (8, 192)
    attn_mma_kernel<<<g2, 256, AT_SMEM_BYTES>>>(out);
}